// round 4
// baseline (speedup 1.0000x reference)
#include <cuda_runtime.h>
#include <math.h>

#define BB    256
#define T2V   1026
#define TP1   1025
#define SSV   1024
#define NVOC  35
#define H7    224
#define HN    (BB*SSV)          /* 262144 valid sampling rows */
#define EPSV  2.220446049250313e-16f
#define LOG2E 1.4426950408889634f
#define LN2   0.6931471805599453f
#define FULLM 0xffffffffu

// ---------------- device scratch ----------------
static __device__ float g_prex[NVOC * H7];
static __device__ float g_intA[BB], g_intB[BB];
static __device__ float g_mskA[BB], g_mskB[BB];
static __device__ float g_loglam[BB], g_nev[BB];

// ---------------- fast math ----------------
__device__ __forceinline__ float ex2f(float x){ float r; asm("ex2.approx.f32 %0,%1;":"=f"(r):"f"(x)); return r; }
__device__ __forceinline__ float lg2f(float x){ float r; asm("lg2.approx.f32 %0,%1;":"=f"(r):"f"(x)); return r; }
__device__ __forceinline__ float rcpf(float x){ float r; asm("rcp.approx.f32 %0,%1;":"=f"(r):"f"(x)); return r; }
__device__ __forceinline__ float sig_fast(float x){ return rcpf(1.0f + ex2f(-x * LOG2E)); }
__device__ __forceinline__ float tanh_fast(float x){ return fmaf(2.0f, rcpf(1.0f + ex2f(-2.0f * LOG2E * x)), -1.0f); }
__device__ __forceinline__ float softplus_fast(float x){
    return fmaxf(x, 0.0f) + lg2f(1.0f + ex2f(-fabsf(x) * LOG2E)) * LN2;
}
// softplus(x)/ln2  (delta kept in log2 domain so decay uses one ex2)
__device__ __forceinline__ float softplus_log2(float x){
    return fmaxf(x, 0.0f) * LOG2E + lg2f(1.0f + ex2f(-fabsf(x) * LOG2E));
}

// ---------------- kernel A: prex[v][j] = Emb[v]·Wx[:,j] + b[j] ------------
__global__ void k_prex(const float* __restrict__ Emb,
                       const float* __restrict__ W,
                       const float* __restrict__ bias) {
    int v = blockIdx.x;
    int j = threadIdx.x;              // 224 threads
    float acc = bias[j];
    #pragma unroll
    for (int k = 0; k < 32; k++)
        acc += Emb[v * 32 + k] * W[k * H7 + j];
    g_prex[v * H7 + j] = acc;
}

// ---------------- fused scan + sampler + target, one CTA per batch --------
// warps 0-6: gate slices; each warp redundantly computes full cell update and
//            keeps its own private h copy in SMEM (hw[w]) -> 1 barrier/step.
// warp 7   : sampler consumer (lags producer by 1 step, lookahead-buffered IO)
// warp 8   : target-loglambda consumer (lags by 1 step, lookahead-buffered IO)
__global__ void __launch_bounds__(288, 2)
k_scan(const int*   __restrict__ event,
       const float* __restrict__ dtime,
       const float* __restrict__ W,
       const float* __restrict__ Wl,
       const float* __restrict__ dts,
       const float* __restrict__ mask,
       float*       __restrict__ lam_out) {
    const int b    = blockIdx.x;
    const int tid  = threadIdx.x;
    const int w    = tid >> 5;
    const int lane = tid & 31;

    __shared__ float prex_sh[NVOC * H7];   // 31.4 KB
    __shared__ float act[2][H7];           // double-buffered activations
    __shared__ float hw[7][32];            // per-warp private h replicas
    __shared__ float ring[2][5][32];       // c,cb,L,o,h for consumers
    __shared__ float wlp[32 * 33];         // padded Wl for target warp
    __shared__ float shch[32];             // sampler transpose

    for (int i = tid; i < NVOC * H7; i += 288) prex_sh[i] = g_prex[i];
    for (int i = tid; i < 1024; i += 288)      wlp[(i >> 5) * 33 + (i & 31)] = Wl[i];

    const int*   evrow = event + b * T2V;
    const float* dtrow = dtime + b * T2V;
    const int    f0    = b * TP1;
    const int    validTp = (HN - f0 < TP1) ? (HN - f0) : TP1;

    // ---- gate-warp state ----
    float wcol[32];
    float cm = 0.0f, cbm = 0.0f;
    int   ev = 0; float dtn = 0.0f;
    if (w < 7) {
        #pragma unroll
        for (int k = 0; k < 32; k++) wcol[k] = W[(32 + k) * H7 + tid];
        ev  = evrow[0];
        dtn = dtrow[1];
        hw[w][lane] = 0.0f;
    }

    // ---- sampler-warp lookahead buffers ----
    float wle[32];
    float dt_cur = 0.f, dt_nxt = 0.f, m_cur = 0.f, m_nxt = 0.f;
    float accLam0 = 0.f, accLam1 = 0.f, accM0 = 0.f, accM1 = 0.f;
    if (w == 7) {
        #pragma unroll
        for (int k = 0; k < 32; k++) wle[k] = Wl[lane * 32 + k];
        int fa = f0 + lane, fb2 = f0 + 32 + lane;
        dt_cur = (fa  < HN) ? dts[fa]   : 0.f;
        m_cur  = (fa  < HN) ? mask[fa]  : 0.f;
        dt_nxt = (fb2 < HN) ? dts[fb2]  : 0.f;
        m_nxt  = (fb2 < HN) ? mask[fb2] : 0.f;
    }
    // ---- target-warp lookahead buffers ----
    int ev_cur = 0, ev_nxt = 0;
    float accL = 0.f, accN = 0.f;
    if (w == 8) {
        ev_cur = evrow[1 + lane];
        ev_nxt = evrow[33 + lane];
    }

    __syncthreads();

    for (int t = 0; t <= TP1; t++) {
        // ---------- phase 1: pre-activations (gate warps, t < TP1) ----------
        if (w < 7 && t < TP1) {
            float pre = prex_sh[ev * H7 + tid];
            const float4* h4 = (const float4*)hw[w];
            float a0 = 0.f, a1 = 0.f, a2 = 0.f, a3 = 0.f;
            #pragma unroll
            for (int q = 0; q < 8; q++) {
                float4 hv = h4[q];                 // broadcast LDS.128
                a0 = fmaf(hv.x, wcol[4 * q + 0], a0);
                a1 = fmaf(hv.y, wcol[4 * q + 1], a1);
                a2 = fmaf(hv.z, wcol[4 * q + 2], a2);
                a3 = fmaf(hv.w, wcol[4 * q + 3], a3);
            }
            pre += (a0 + a1) + (a2 + a3);

            float a;
            if (w == 2)      a = tanh_fast(pre);      // z
            else if (w == 6) a = softplus_log2(pre);  // delta (log2 domain)
            else             a = sig_fast(pre);       // i,f,o,ib,fb
            act[t & 1][tid] = a;

            int ti = t + 1; if (ti > TP1) ti = TP1;
            ev = evrow[ti];                            // prefetch (cached)
        }
        __syncthreads();

        // ---------- phase 2 / consumers ----------
        if (w < 7) {
            if (t < TP1) {
                const float* A = act[t & 1];
                float iv  = A[lane];
                float fv  = A[32  + lane];
                float zv  = A[64  + lane];
                float ov  = A[96  + lane];
                float ibv = A[128 + lane];
                float fbv = A[160 + lane];
                float L   = A[192 + lane];

                float c  = fmaf(fv,  cm,  iv  * zv);
                float cb = fmaf(fbv, cbm, ibv * zv);
                float e  = ex2f(-L * dtn);
                float cn = fmaf(c - cb, e, cb);
                float h  = ov * tanh_fast(cn);

                // distributed ring stores (one STS per warp)
                int s = t & 1;
                if      (w == 0) ring[s][0][lane] = c;
                else if (w == 1) ring[s][1][lane] = cb;
                else if (w == 2) ring[s][2][lane] = L;
                else if (w == 3) ring[s][3][lane] = ov;
                else if (w == 4) ring[s][4][lane] = h;

                hw[w][lane] = h;
                __syncwarp();

                cm = cn; cbm = cb;
                int ti = t + 2; if (ti > T2V - 1) ti = T2V - 1;
                dtn = dtrow[ti];
            }
        } else if (w == 7) {
            if (t > 0) {
                int tp = t - 1;
                if (tp < validTp) {
                    if ((tp & 31) == 0 && tp > 0) {     // rotate lookahead
                        dt_cur = dt_nxt; m_cur = m_nxt;
                        int fn = f0 + tp + 32 + lane;
                        bool ok = fn < HN;
                        dt_nxt = ok ? dts[fn]  : 0.f;
                        m_nxt  = ok ? mask[fn] : 0.f;
                    }
                    float dtv = __shfl_sync(FULLM, dt_cur, tp & 31);
                    float m   = __shfl_sync(FULLM, m_cur,  tp & 31);

                    int s = tp & 1;
                    float c  = ring[s][0][lane];
                    float cb = ring[s][1][lane];
                    float L  = ring[s][2][lane];
                    float o  = ring[s][3][lane];
                    float e  = ex2f(-L * dtv);
                    float cd = fmaf(c - cb, e, cb);
                    float ch = o * tanh_fast(cd);
                    shch[lane] = ch;
                    __syncwarp();
                    float d0 = 0.f, d1 = 0.f, d2 = 0.f, d3 = 0.f;
                    #pragma unroll
                    for (int q = 0; q < 8; q++) {
                        float4 c4 = ((const float4*)shch)[q];   // broadcast
                        d0 = fmaf(c4.x, wle[4 * q + 0], d0);
                        d1 = fmaf(c4.y, wle[4 * q + 1], d1);
                        d2 = fmaf(c4.z, wle[4 * q + 2], d2);
                        d3 = fmaf(c4.w, wle[4 * q + 3], d3);
                    }
                    float sp = softplus_fast((d0 + d1) + (d2 + d3));
                    lam_out[(size_t)(f0 + tp) * 32 + lane] = sp;
                    if (b + tp < 1024) { accLam0 += sp * m; if (lane == 0) accM0 += m; }
                    else               { accLam1 += sp * m; if (lane == 0) accM1 += m; }
                    __syncwarp();
                }
            }
        } else { // w == 8: target log-lambda
            if (t > 0) {
                int tp = t - 1;
                if ((tp & 31) == 0 && tp > 0) {          // rotate lookahead
                    ev_cur = ev_nxt;
                    int idx = 1 + tp + 32 + lane; if (idx > TP1) idx = TP1;
                    ev_nxt = evrow[idx];
                }
                int tgt = __shfl_sync(FULLM, ev_cur, tp & 31);
                bool mm = (tgt < 32);
                int  tt = mm ? tgt : 0;
                float p = ring[tp & 1][4][lane] * wlp[tt * 33 + lane];
                #pragma unroll
                for (int o = 16; o > 0; o >>= 1) p += __shfl_down_sync(FULLM, p, o);
                if (lane == 0 && mm) {
                    accL += lg2f(softplus_fast(p) + EPSV) * LN2;
                    accN += 1.0f;
                }
            }
        }
    }

    // ---------- per-CTA epilogue ----------
    if (w == 7) {
        #pragma unroll
        for (int o = 16; o > 0; o >>= 1) {
            accLam0 += __shfl_down_sync(FULLM, accLam0, o);
            accLam1 += __shfl_down_sync(FULLM, accLam1, o);
        }
        if (lane == 0) {
            g_intA[b] = accLam0; g_intB[b] = accLam1;
            g_mskA[b] = accM0;   g_mskB[b] = accM1;
        }
    } else if (w == 8 && lane == 0) {
        g_loglam[b] = accL;
        g_nev[b]    = accN;
    }
}

// ---------------- final: stitch integral groups + reduce scalars ----------
__global__ void __launch_bounds__(256)
k_final(const float* __restrict__ dur, float* __restrict__ out) {
    const int bb = threadIdx.x;     // one thread per group
    __shared__ float red[8];

    float lamsum = g_intA[bb] + (bb > 0 ? g_intB[bb - 1] : 0.0f);
    float msum   = g_mskA[bb] + (bb > 0 ? g_mskB[bb - 1] : 0.0f);
    float integ  = __fdividef(lamsum, msum) * dur[bb];
    float lp = g_loglam[bb] - integ;
    float nv = g_nev[bb];

    #pragma unroll
    for (int o = 16; o > 0; o >>= 1) lp += __shfl_down_sync(FULLM, lp, o);
    int wid = threadIdx.x >> 5, lid = threadIdx.x & 31;
    if (lid == 0) red[wid] = lp;
    __syncthreads();
    if (wid == 0) {
        float v = (lid < 8) ? red[lid] : 0.0f;
        #pragma unroll
        for (int o = 4; o > 0; o >>= 1) v += __shfl_down_sync(FULLM, v, o);
        if (lid == 0) out[0] = -v;
    }
    __syncthreads();
    #pragma unroll
    for (int o = 16; o > 0; o >>= 1) nv += __shfl_down_sync(FULLM, nv, o);
    if (lid == 0) red[wid] = nv;
    __syncthreads();
    if (wid == 0) {
        float v = (lid < 8) ? red[lid] : 0.0f;
        #pragma unroll
        for (int o = 4; o > 0; o >>= 1) v += __shfl_down_sync(FULLM, v, o);
        if (lid == 0) out[1] = v;
    }
}

// ---------------- launch ----------------
extern "C" void kernel_launch(void* const* d_in, const int* in_sizes, int n_in,
                              void* d_out, int out_size) {
    const int*   event = (const int*)  d_in[0];
    const float* dtime = (const float*)d_in[1];
    const float* dur   = (const float*)d_in[2];
    const float* dts   = (const float*)d_in[3];
    // d_in[4] = index_of_hidden_sampling (unused by the reference)
    const float* mask  = (const float*)d_in[5];
    const float* Emb   = (const float*)d_in[6];
    const float* W     = (const float*)d_in[7];
    const float* bias  = (const float*)d_in[8];
    const float* Wl    = (const float*)d_in[9];

    float* out = (float*)d_out;
    long long lam_elems = (long long)HN * 32;
    long long lamoff = (long long)out_size - lam_elems;
    if (lamoff < 0) lamoff = 0;
    float* lam_out = out + lamoff;

    k_prex <<<NVOC, H7>>>(Emb, W, bias);
    k_scan <<<BB, 288>>>(event, dtime, W, Wl, dts, mask, lam_out);
    k_final<<<1, 256>>>(dur, out);
}